// round 12
// baseline (speedup 1.0000x reference)
#include <cuda_runtime.h>
#include <cuda_fp16.h>
#include <math.h>

// ---------------- problem constants ----------------
#define BSZ   32
#define CCH   256
#define NPIX  4096      // 64x64

// ---------------- scratch (device globals; no allocation) ----------------
__device__ __align__(16) __half  g_yt[(size_t)BSZ * CCH * NPIX];   // conv out fp16
__device__ __align__(16) __half  g_xt[(size_t)BSZ * NPIX * CCH];   // x transposed fp16
__device__ __align__(16) __half  g_wa[9 * CCH * CCH];              // weights fp16
__device__ __align__(16) __half  g_gyT[CCH * 4096];                // GyT[c][j][q] fp16
__device__ __align__(16) __half  g_gx[CCH * 4096];                 // Gx[c][i][h] fp16

// ---------------- helpers ----------------
__device__ __forceinline__ unsigned smem_u32(const void* p) {
    unsigned r;
    asm("{ .reg .u64 t; cvta.to.shared.u64 t, %1; cvt.u32.u64 %0, t; }" : "=r"(r) : "l"(p));
    return r;
}
__device__ __forceinline__ unsigned sw128(unsigned off) { return off ^ ((off >> 3) & 0x70); }

__device__ __forceinline__ void ldm_x4(unsigned* r, unsigned addr) {
    asm volatile("ldmatrix.sync.aligned.m8n8.x4.shared.b16 {%0,%1,%2,%3}, [%4];"
        : "=r"(r[0]), "=r"(r[1]), "=r"(r[2]), "=r"(r[3]) : "r"(addr));
}
__device__ __forceinline__ void mma_f16(float* d, const unsigned* a,
                                        unsigned b0, unsigned b1) {
    asm volatile("mma.sync.aligned.m16n8k16.row.col.f32.f16.f16.f32 "
        "{%0,%1,%2,%3}, {%4,%5,%6,%7}, {%8,%9}, {%0,%1,%2,%3};"
        : "+f"(d[0]), "+f"(d[1]), "+f"(d[2]), "+f"(d[3])
        : "r"(a[0]), "r"(a[1]), "r"(a[2]), "r"(a[3]), "r"(b0), "r"(b1));
}
__device__ __forceinline__ void cp16(unsigned dst, const void* src) {
    asm volatile("cp.async.cg.shared.global [%0], [%1], 16;" :: "r"(dst), "l"(src));
}
__device__ __forceinline__ void cp16z(unsigned dst, const void* src, bool ok) {
    int sz = ok ? 16 : 0;
    asm volatile("cp.async.cg.shared.global [%0], [%1], 16, %2;"
                 :: "r"(dst), "l"(src), "r"(sz));
}
__device__ __forceinline__ void cp_commit() {
    asm volatile("cp.async.commit_group;" ::: "memory");
}
__device__ __forceinline__ void cp_wait0() {
    asm volatile("cp.async.wait_group 0;" ::: "memory");
}
__device__ __forceinline__ unsigned pk_h2(float a, float b) {
    __half ha = __float2half_rn(a), hb = __float2half_rn(b);
    return (unsigned)__half_as_ushort(ha) | ((unsigned)__half_as_ushort(hb) << 16);
}

// ---------------- kernel 1: weights -> [tap][co][ci] fp16 ----------------
__global__ void wa_kernel(const float* __restrict__ w) {
    __shared__ float s[2304];
    const int co  = blockIdx.x;
    const int tid = threadIdx.x;
    for (int i = tid; i < 2304; i += 256) s[i] = w[(size_t)co * 2304 + i];
    __syncthreads();
    for (int it = tid; it < 288; it += 256) {
        int tap = it >> 5, grp = it & 31;
        unsigned h4[4];
        #pragma unroll
        for (int k = 0; k < 4; k++)
            h4[k] = pk_h2(s[(grp * 8 + k * 2) * 9 + tap],
                          s[(grp * 8 + k * 2 + 1) * 9 + tap]);
        size_t o = ((size_t)tap * 256 + co) * 256 + grp * 8;
        *(uint4*)(g_wa + o) = make_uint4(h4[0], h4[1], h4[2], h4[3]);
    }
}

// ---------------- kernel 2: circulant inverse + matrices (merged, fp16) ----------------
__global__ void gmat_kernel(const float* __restrict__ alpha) {
    __shared__ float gx[64], gy[64];
    const int c   = blockIdx.x;
    const int tid = threadIdx.x;      // 128 threads

    if (tid < 128) {
        int dir = tid >> 6;
        int n   = tid & 63;
        float t00 = tanhf(alpha[c*4+0]), t01 = tanhf(alpha[c*4+1]);
        float t10 = tanhf(alpha[c*4+2]), t11 = tanhf(alpha[c*4+3]);
        const float R = 0.70710678118654752440f;
        float a0, a2;
        if (dir == 0) { a0 = (t00 + t01) * R; a2 = (t01 - t00) * R; }
        else          { a0 = (t10 + t11) * R; a2 = (t11 - t10) * R; }
        double ar = (double)a0 + (double)a2;
        double ai = (double)a0 - (double)a2;
        double s = 0.0;
        for (int u = 0; u < 64; u++) {
            double th  = (2.0 * 3.14159265358979323846 / 64.0) * (double)u;
            double Fre = 1.0 + ar * cos(th);
            double Fim = ai * sin(th);
            double den = Fre * Fre + Fim * Fim;
            double ang = th * (double)n;
            s += (cos(ang) * Fre + sin(ang) * Fim) / den;
        }
        float g = (float)(s / 64.0);
        if (dir == 0) gx[n] = g; else gy[n] = g;
    }
    __syncthreads();

    for (int i = tid; i < 512; i += 128) {      // 64 rows x 8 q-groups
        int r = i >> 3, grp = i & 7;
        unsigned x4[4], y4[4];
        #pragma unroll
        for (int k = 0; k < 4; k++) {
            int q0 = grp * 8 + k * 2;
            x4[k] = pk_h2(gx[(r - q0) & 63], gx[(r - q0 - 1) & 63]);
            y4[k] = pk_h2(gy[(r - q0) & 63], gy[(r - q0 - 1) & 63]);
        }
        size_t o = (size_t)c * 4096 + r * 64 + grp * 8;
        *(uint4*)(g_gx  + o) = make_uint4(x4[0], x4[1], x4[2], x4[3]);
        *(uint4*)(g_gyT + o) = make_uint4(y4[0], y4[1], y4[2], y4[3]);
    }
}

// ---------------- kernel 3: x -> transposed fp16 ----------------
__global__ void xt_kernel(const float* __restrict__ x) {
    __shared__ float s[64][65];
    int p0  = blockIdx.x * 64;
    int ci0 = blockIdx.y * 64;
    int b   = blockIdx.z;
    int tid = threadIdx.x;
    for (int i = tid; i < 1024; i += 256) {
        int ci = i >> 4, p4 = (i & 15) << 2;
        float4 v = *(const float4*)(x + ((size_t)(b * 256 + ci0 + ci)) * NPIX + p0 + p4);
        s[ci][p4 + 0] = v.x; s[ci][p4 + 1] = v.y;
        s[ci][p4 + 2] = v.z; s[ci][p4 + 3] = v.w;
    }
    __syncthreads();
    for (int i = tid; i < 512; i += 256) {
        int pix = i >> 3, grp = i & 7;
        unsigned h4[4];
        #pragma unroll
        for (int k = 0; k < 4; k++)
            h4[k] = pk_h2(s[grp * 8 + k * 2][pix], s[grp * 8 + k * 2 + 1][pix]);
        size_t o = ((size_t)b * NPIX + p0 + pix) * 256 + ci0 + grp * 8;
        *(uint4*)(g_xt + o) = make_uint4(h4[0], h4[1], h4[2], h4[3]);
    }
}

// ---------------- kernel 4: implicit-GEMM conv, single-term fp16 ----------------
#define XP_ROWS  (4 * 68)
#define XP_BYTES (XP_ROWS * 128)       // 34816
#define OFF_X  0u
#define OFF_A0 34816u
#define A_BUF  16384u
#define CONV_SMEM (OFF_A0 + 2 * A_BUF) // 67584

__global__ __launch_bounds__(256, 2)
void conv_mma_kernel() {
    extern __shared__ char smem[];
    const unsigned sb = smem_u32(smem);
    const int tid = threadIdx.x;
    const int lid = tid & 31;
    const int wid = tid >> 5;
    const int wm  = wid & 3;
    const int wn  = wid >> 2;

    const int n0  = blockIdx.x * 128;
    const int h0  = n0 >> 6;
    const int co0 = blockIdx.y * 128;
    const int b   = blockIdx.z;

    const __half* xp = g_xt + (size_t)b * NPIX * 256;

    float acc[2][8][4];
    #pragma unroll
    for (int mt = 0; mt < 2; mt++)
        #pragma unroll
        for (int nt = 0; nt < 8; nt++)
            #pragma unroll
            for (int k = 0; k < 4; k++) acc[mt][nt][k] = 0.f;

    unsigned a_rowoff[2];
    #pragma unroll
    for (int mt = 0; mt < 2; mt++) {
        int row = wm * 32 + mt * 16 + (lid & 7) + ((lid >> 3) & 1) * 8;
        a_rowoff[mt] = (unsigned)(row * 128) + ((unsigned)(lid >> 4)) * 16u;
    }
    int bn[4];
    #pragma unroll
    for (int j = 0; j < 4; j++) bn[j] = wn * 64 + j * 16 + (lid & 15);
    const unsigned bk8 = ((unsigned)(lid >> 4)) * 16u;

    auto stageA = [&](int tap, int ci0, int s) {
        unsigned dH = sb + OFF_A0 + (unsigned)s * A_BUF;
        #pragma unroll
        for (int i = tid; i < 1024; i += 256) {
            int cq = i & 7, row = i >> 3;
            size_t src = ((size_t)tap * 256 + co0 + row) * 256 + ci0 + cq * 8;
            cp16(dH + sw128((unsigned)(row * 128 + cq * 16)), g_wa + src);
        }
        cp_commit();
    };

    for (int cc = 0; cc < 4; cc++) {
        const int ci0 = cc << 6;
        __syncthreads();
        for (int i = tid; i < 4 * 66 * 8; i += 256) {
            int cq  = i & 7;
            int row = i >> 3;
            int hl  = row / 66;
            int wv  = row - hl * 66;
            int h = h0 + hl - 1;
            int w = wv - 1;
            bool ok = ((unsigned)h < 64u) && ((unsigned)w < 64u);
            size_t src = ok ? (((size_t)(h * 64 + w)) * 256 + ci0 + cq * 8) : 0;
            cp16z(sb + OFF_X + sw128((unsigned)((hl * 68 + wv) * 128 + cq * 16)),
                  xp + src, ok);
        }
        stageA(0, ci0, 0);
        cp_wait0();
        __syncthreads();

        for (int tap = 0; tap < 9; tap++) {
            const int s  = tap & 1;
            const int dh = tap / 3 - 1;
            const int dw = tap % 3 - 1;
            if (tap < 8) stageA(tap + 1, ci0, s ^ 1);

            const unsigned AH = sb + OFF_A0 + (unsigned)s * A_BUF;

            unsigned b_rowoff[4];
            #pragma unroll
            for (int j = 0; j < 4; j++) {
                int hl = bn[j] >> 6, w = bn[j] & 63;
                b_rowoff[j] = (unsigned)(((hl + dh + 1) * 68 + (w + dw + 1)) * 128) + bk8;
            }

            #pragma unroll
            for (int ks = 0; ks < 4; ks++) {
                unsigned af[2][4], bf[4][4];
                #pragma unroll
                for (int mt = 0; mt < 2; mt++)
                    ldm_x4(af[mt], AH + sw128(a_rowoff[mt] + ks * 32u));
                #pragma unroll
                for (int j = 0; j < 4; j++)
                    ldm_x4(bf[j], sb + OFF_X + sw128(b_rowoff[j] + ks * 32u));
                #pragma unroll
                for (int mt = 0; mt < 2; mt++)
                    #pragma unroll
                    for (int nt = 0; nt < 8; nt++)
                        mma_f16(acc[mt][nt], af[mt],
                                bf[nt >> 1][nt & 1], bf[nt >> 1][(nt & 1) + 2]);
            }
            if (tap < 8) {
                cp_wait0();
                __syncthreads();
            }
        }
    }

    const int r4 = lid >> 2, c2 = (lid & 3) << 1;
    #pragma unroll
    for (int mt = 0; mt < 2; mt++) {
        #pragma unroll
        for (int nt = 0; nt < 8; nt++) {
            int co  = co0 + wm * 32 + mt * 16 + r4;
            int pix = n0 + wn * 64 + nt * 8 + c2;
            size_t base = ((size_t)(b * 256 + co)) * NPIX + pix;
            *(unsigned*)(g_yt + base) = pk_h2(acc[mt][nt][0], acc[mt][nt][1]);
            *(unsigned*)(g_yt + base + (size_t)8 * NPIX) =
                pk_h2(acc[mt][nt][2], acc[mt][nt][3]);
        }
    }
}

// ---------------- kernel 5: ARMA solve, 4 slices/CTA, warp-per-slice ----------------
// Warp w owns slice (grp*4 + w)*256 + c. Stage1: UT[j][h] = sum_q GyT[j][q]*Y[h][q]
// (warp tile M64 x N64). UT overwrites the slice's Y region (warp-private).
// Stage2: out[i][j] = sum_h Gx[i][h]*UT[j][h]. No CTA barriers after staging.
#define PA_Y  0u                        // 4 x 8192
#define PA_GY 32768u
#define PA_GX 40960u
#define ARMA_SMEM 49152

__global__ __launch_bounds__(128, 2)
void arma_mma_kernel(float* __restrict__ out) {
    extern __shared__ char smem[];
    const unsigned sb = smem_u32(smem);
    const int tid = threadIdx.x;
    const int lid = tid & 31;
    const int wid = tid >> 5;           // 0..3 = slice within group
    const int c   = blockIdx.x & 255;
    const int grp = blockIdx.x >> 8;    // 0..7
    const int slice0 = (grp * 4) * 256 + c;

    // ---- stage inputs: Y (4 slices) + G matrices ----
    for (int i = tid; i < 2048; i += 128) {
        int r = i >> 3, cq = i & 7;          // r = slice*64 + h
        int s = r >> 6, h = r & 63;
        size_t e = ((size_t)(slice0 + s * 256)) * 4096 + h * 64 + cq * 8;
        cp16(sb + PA_Y + sw128((unsigned)(r * 128 + cq * 16)), g_yt + e);
    }
    for (int i = tid; i < 512; i += 128) {
        int r = i >> 3, cq = i & 7;
        size_t e = (size_t)c * 4096 + r * 64 + cq * 8;
        unsigned swo = sw128((unsigned)(r * 128 + cq * 16));
        cp16(sb + PA_GY + swo, g_gyT + e);
        cp16(sb + PA_GX + swo, g_gx  + e);
    }
    cp_commit(); cp_wait0();
    __syncthreads();                     // last CTA-wide barrier

    // lane geometry
    unsigned a_rowoff[4];
    #pragma unroll
    for (int mt = 0; mt < 4; mt++) {
        int row = mt * 16 + (lid & 7) + ((lid >> 3) & 1) * 8;
        a_rowoff[mt] = (unsigned)(row * 128) + ((unsigned)(lid >> 4)) * 16u;
    }
    unsigned b_off[4];
    #pragma unroll
    for (int j = 0; j < 4; j++)
        b_off[j] = (unsigned)((wid * 64 + j * 16 + (lid & 15)) * 128)
                 + ((unsigned)(lid >> 4)) * 16u;
    const int r4 = lid >> 2, cp2 = (lid & 3) << 1;
    const unsigned yreg = sb + PA_Y;     // b_off already includes wid*64 rows

    // ---- stage 1: UT = GyT x Y (M=j, N=h) ----
    float acc[4][8][4];
    #pragma unroll
    for (int mt = 0; mt < 4; mt++)
        #pragma unroll
        for (int nt = 0; nt < 8; nt++)
            #pragma unroll
            for (int k = 0; k < 4; k++) acc[mt][nt][k] = 0.f;

    #pragma unroll
    for (int ks = 0; ks < 4; ks++) {
        unsigned A[4][4], B[4][4];
        #pragma unroll
        for (int mt = 0; mt < 4; mt++)
            ldm_x4(A[mt], sb + PA_GY + sw128(a_rowoff[mt] + ks * 32u));
        #pragma unroll
        for (int j = 0; j < 4; j++)
            ldm_x4(B[j], yreg + sw128(b_off[j] + ks * 32u));
        #pragma unroll
        for (int mt = 0; mt < 4; mt++)
            #pragma unroll
            for (int nt = 0; nt < 8; nt++)
                mma_f16(acc[mt][nt], A[mt],
                        B[nt >> 1][nt & 1], B[nt >> 1][(nt & 1) + 2]);
    }
    __syncwarp();        // all lanes of this warp done reading their Y region

    // write UT[j][h] into this warp's Y region (row = j, col = h)
    #pragma unroll
    for (int mt = 0; mt < 4; mt++) {
        #pragma unroll
        for (int nt = 0; nt < 8; nt++) {
            int m = mt * 16 + r4;
            int n = nt * 8 + cp2;
            unsigned base = (unsigned)(wid * 8192);
            *(unsigned*)(smem + PA_Y + base + sw128((unsigned)(m * 128 + n * 2))) =
                pk_h2(acc[mt][nt][0], acc[mt][nt][1]);
            *(unsigned*)(smem + PA_Y + base + sw128((unsigned)((m + 8) * 128 + n * 2))) =
                pk_h2(acc[mt][nt][2], acc[mt][nt][3]);
        }
    }
    __syncwarp();

    // ---- stage 2: out = Gx x UT (M=i, N=j) ----
    float o[4][8][4];
    #pragma unroll
    for (int mt = 0; mt < 4; mt++)
        #pragma unroll
        for (int nt = 0; nt < 8; nt++)
            #pragma unroll
            for (int k = 0; k < 4; k++) o[mt][nt][k] = 0.f;

    #pragma unroll
    for (int ks = 0; ks < 4; ks++) {
        unsigned A[4][4], B[4][4];
        #pragma unroll
        for (int mt = 0; mt < 4; mt++)
            ldm_x4(A[mt], sb + PA_GX + sw128(a_rowoff[mt] + ks * 32u));
        #pragma unroll
        for (int j = 0; j < 4; j++)
            ldm_x4(B[j], yreg + sw128(b_off[j] + ks * 32u));
        #pragma unroll
        for (int mt = 0; mt < 4; mt++)
            #pragma unroll
            for (int nt = 0; nt < 8; nt++)
                mma_f16(o[mt][nt], A[mt],
                        B[nt >> 1][nt & 1], B[nt >> 1][(nt & 1) + 2]);
    }

    // epilogue: out[i][j] for slice (grp*4 + wid)
    float* O = out + ((size_t)(slice0 + wid * 256)) * 4096;
    #pragma unroll
    for (int mt = 0; mt < 4; mt++) {
        #pragma unroll
        for (int nt = 0; nt < 8; nt++) {
            int m = mt * 16 + r4;
            int j = nt * 8 + cp2;
            *(float2*)(O + m * 64 + j)       = make_float2(o[mt][nt][0], o[mt][nt][1]);
            *(float2*)(O + (m + 8) * 64 + j) = make_float2(o[mt][nt][2], o[mt][nt][3]);
        }
    }
}

// ---------------- launcher ----------------
extern "C" void kernel_launch(void* const* d_in, const int* in_sizes, int n_in,
                              void* d_out, int out_size) {
    const float* x     = (const float*)d_in[0];
    const float* w     = (const float*)d_in[1];
    const float* alpha = (const float*)d_in[2];
    float* out = (float*)d_out;

    cudaFuncSetAttribute(conv_mma_kernel,
                         cudaFuncAttributeMaxDynamicSharedMemorySize, CONV_SMEM);
    cudaFuncSetAttribute(arma_mma_kernel,
                         cudaFuncAttributeMaxDynamicSharedMemorySize, ARMA_SMEM);

    wa_kernel<<<CCH, 256>>>(w);                       // launch 0
    gmat_kernel<<<CCH, 128>>>(alpha);                 // launch 1
    xt_kernel<<<dim3(64, 4, 32), 256>>>(x);           // launch 2
    conv_mma_kernel<<<dim3(32, 2, 32), 256, CONV_SMEM>>>();   // launch 3 (profiled slot)
    arma_mma_kernel<<<8 * 256, 128, ARMA_SMEM>>>(out);        // launch 4
}

// round 13
// speedup vs baseline: 1.8133x; 1.8133x over previous
#include <cuda_runtime.h>
#include <cuda_fp16.h>
#include <math.h>

// ---------------- problem constants ----------------
#define BSZ   32
#define CCH   256
#define NPIX  4096      // 64x64

// ---------------- scratch (device globals; no allocation) ----------------
__device__ __align__(16) __half  g_yt[(size_t)BSZ * CCH * NPIX];   // conv out fp16
__device__ __align__(16) __half  g_xt[(size_t)BSZ * NPIX * CCH];   // x transposed fp16
__device__ __align__(16) __half  g_wa[9 * CCH * CCH];              // weights fp16
__device__ __align__(16) __half  g_gyT[CCH * 4096];                // GyT[c][j][q] fp16
__device__ __align__(16) __half  g_gx[CCH * 4096];                 // Gx[c][i][h] fp16

// ---------------- helpers ----------------
__device__ __forceinline__ unsigned smem_u32(const void* p) {
    unsigned r;
    asm("{ .reg .u64 t; cvta.to.shared.u64 t, %1; cvt.u32.u64 %0, t; }" : "=r"(r) : "l"(p));
    return r;
}
__device__ __forceinline__ unsigned sw128(unsigned off) { return off ^ ((off >> 3) & 0x70); }

__device__ __forceinline__ void ldm_x4(unsigned* r, unsigned addr) {
    asm volatile("ldmatrix.sync.aligned.m8n8.x4.shared.b16 {%0,%1,%2,%3}, [%4];"
        : "=r"(r[0]), "=r"(r[1]), "=r"(r[2]), "=r"(r[3]) : "r"(addr));
}
__device__ __forceinline__ void mma_f16(float* d, const unsigned* a,
                                        unsigned b0, unsigned b1) {
    asm volatile("mma.sync.aligned.m16n8k16.row.col.f32.f16.f16.f32 "
        "{%0,%1,%2,%3}, {%4,%5,%6,%7}, {%8,%9}, {%0,%1,%2,%3};"
        : "+f"(d[0]), "+f"(d[1]), "+f"(d[2]), "+f"(d[3])
        : "r"(a[0]), "r"(a[1]), "r"(a[2]), "r"(a[3]), "r"(b0), "r"(b1));
}
__device__ __forceinline__ void cp16(unsigned dst, const void* src) {
    asm volatile("cp.async.cg.shared.global [%0], [%1], 16;" :: "r"(dst), "l"(src));
}
__device__ __forceinline__ void cp16z(unsigned dst, const void* src, bool ok) {
    int sz = ok ? 16 : 0;
    asm volatile("cp.async.cg.shared.global [%0], [%1], 16, %2;"
                 :: "r"(dst), "l"(src), "r"(sz));
}
__device__ __forceinline__ void cp_commit() {
    asm volatile("cp.async.commit_group;" ::: "memory");
}
__device__ __forceinline__ void cp_wait0() {
    asm volatile("cp.async.wait_group 0;" ::: "memory");
}
__device__ __forceinline__ unsigned pk_h2(float a, float b) {
    __half ha = __float2half_rn(a), hb = __float2half_rn(b);
    return (unsigned)__half_as_ushort(ha) | ((unsigned)__half_as_ushort(hb) << 16);
}

// ---------------- kernel 1: weights -> [tap][co][ci] fp16 ----------------
__global__ void wa_kernel(const float* __restrict__ w) {
    __shared__ float s[2304];
    const int co  = blockIdx.x;
    const int tid = threadIdx.x;
    for (int i = tid; i < 2304; i += 256) s[i] = w[(size_t)co * 2304 + i];
    __syncthreads();
    for (int it = tid; it < 288; it += 256) {
        int tap = it >> 5, grp = it & 31;
        unsigned h4[4];
        #pragma unroll
        for (int k = 0; k < 4; k++)
            h4[k] = pk_h2(s[(grp * 8 + k * 2) * 9 + tap],
                          s[(grp * 8 + k * 2 + 1) * 9 + tap]);
        size_t o = ((size_t)tap * 256 + co) * 256 + grp * 8;
        *(uint4*)(g_wa + o) = make_uint4(h4[0], h4[1], h4[2], h4[3]);
    }
}

// ---------------- kernel 2: circulant inverse + matrices (float recurrences) ----------------
__global__ void gmat_kernel(const float* __restrict__ alpha) {
    __shared__ float gx[64], gy[64];
    const int c   = blockIdx.x;
    const int tid = threadIdx.x;      // 128 threads

    {
        int dir = tid >> 6;
        int n   = tid & 63;
        float t00 = tanhf(alpha[c*4+0]), t01 = tanhf(alpha[c*4+1]);
        float t10 = tanhf(alpha[c*4+2]), t11 = tanhf(alpha[c*4+3]);
        const float R = 0.70710678118654752440f;
        float a0, a2;
        if (dir == 0) { a0 = (t00 + t01) * R; a2 = (t01 - t00) * R; }
        else          { a0 = (t10 + t11) * R; a2 = (t11 - t10) * R; }
        float ar = a0 + a2;
        float ai = a0 - a2;

        const float dth = 6.28318530717958647692f / 64.0f;
        float s1, c1;  sincosf(dth, &s1, &c1);
        float sn, cn;  sincosf(dth * (float)n, &sn, &cn);
        float cu = 1.f, su = 0.f;     // cos/sin of th_u
        float ca = 1.f, sa = 0.f;     // cos/sin of th_u * n
        float acc = 0.f;
        #pragma unroll 4
        for (int u = 0; u < 64; u++) {
            float Fre = 1.f + ar * cu;
            float Fim = ai * su;
            float den = Fre * Fre + Fim * Fim;
            acc += (ca * Fre + sa * Fim) / den;
            float t;
            t = cu * c1 - su * s1;  su = su * c1 + cu * s1;  cu = t;
            t = ca * cn - sa * sn;  sa = sa * cn + ca * sn;  ca = t;
        }
        float g = acc * (1.0f / 64.0f);
        if (dir == 0) gx[n] = g; else gy[n] = g;
    }
    __syncthreads();

    for (int i = tid; i < 512; i += 128) {      // 64 rows x 8 q-groups
        int r = i >> 3, grp = i & 7;
        unsigned x4[4], y4[4];
        #pragma unroll
        for (int k = 0; k < 4; k++) {
            int q0 = grp * 8 + k * 2;
            x4[k] = pk_h2(gx[(r - q0) & 63], gx[(r - q0 - 1) & 63]);
            y4[k] = pk_h2(gy[(r - q0) & 63], gy[(r - q0 - 1) & 63]);
        }
        size_t o = (size_t)c * 4096 + r * 64 + grp * 8;
        *(uint4*)(g_gx  + o) = make_uint4(x4[0], x4[1], x4[2], x4[3]);
        *(uint4*)(g_gyT + o) = make_uint4(y4[0], y4[1], y4[2], y4[3]);
    }
}

// ---------------- kernel 3: x -> transposed fp16 ----------------
__global__ void xt_kernel(const float* __restrict__ x) {
    __shared__ float s[64][65];
    int p0  = blockIdx.x * 64;
    int ci0 = blockIdx.y * 64;
    int b   = blockIdx.z;
    int tid = threadIdx.x;
    for (int i = tid; i < 1024; i += 256) {
        int ci = i >> 4, p4 = (i & 15) << 2;
        float4 v = *(const float4*)(x + ((size_t)(b * 256 + ci0 + ci)) * NPIX + p0 + p4);
        s[ci][p4 + 0] = v.x; s[ci][p4 + 1] = v.y;
        s[ci][p4 + 2] = v.z; s[ci][p4 + 3] = v.w;
    }
    __syncthreads();
    for (int i = tid; i < 512; i += 256) {
        int pix = i >> 3, grp = i & 7;
        unsigned h4[4];
        #pragma unroll
        for (int k = 0; k < 4; k++)
            h4[k] = pk_h2(s[grp * 8 + k * 2][pix], s[grp * 8 + k * 2 + 1][pix]);
        size_t o = ((size_t)b * NPIX + p0 + pix) * 256 + ci0 + grp * 8;
        *(uint4*)(g_xt + o) = make_uint4(h4[0], h4[1], h4[2], h4[3]);
    }
}

// ---------------- kernel 4: implicit-GEMM conv, single fp16, 4-buf A ring ----------------
// CTA: M=128 co x N=128 pixels. 256 threads = 8 warps (4M x 2N), warp tile 32x64.
// A ring of 4 buffers; barriers only at chunk start + after odd taps.
#define XP_ROWS  (4 * 68)
#define XP_BYTES (XP_ROWS * 128)       // 34816
#define OFF_X  0u
#define OFF_A0 34816u
#define A_BUF  16384u
#define CONV_SMEM (OFF_A0 + 4 * A_BUF) // 100352

__global__ __launch_bounds__(256, 2)
void conv_mma_kernel() {
    extern __shared__ char smem[];
    const unsigned sb = smem_u32(smem);
    const int tid = threadIdx.x;
    const int lid = tid & 31;
    const int wid = tid >> 5;
    const int wm  = wid & 3;
    const int wn  = wid >> 2;

    const int n0  = blockIdx.x * 128;
    const int h0  = n0 >> 6;
    const int co0 = blockIdx.y * 128;
    const int b   = blockIdx.z;

    const __half* xp = g_xt + (size_t)b * NPIX * 256;

    float acc[2][8][4];
    #pragma unroll
    for (int mt = 0; mt < 2; mt++)
        #pragma unroll
        for (int nt = 0; nt < 8; nt++)
            #pragma unroll
            for (int k = 0; k < 4; k++) acc[mt][nt][k] = 0.f;

    unsigned a_rowoff[2];
    #pragma unroll
    for (int mt = 0; mt < 2; mt++) {
        int row = wm * 32 + mt * 16 + (lid & 7) + ((lid >> 3) & 1) * 8;
        a_rowoff[mt] = (unsigned)(row * 128) + ((unsigned)(lid >> 4)) * 16u;
    }
    int bn[4];
    #pragma unroll
    for (int j = 0; j < 4; j++) bn[j] = wn * 64 + j * 16 + (lid & 15);
    const unsigned bk8 = ((unsigned)(lid >> 4)) * 16u;

    auto stageA = [&](int tap, int ci0, int s) {
        unsigned dH = sb + OFF_A0 + (unsigned)s * A_BUF;
        #pragma unroll
        for (int i = tid; i < 1024; i += 256) {
            int cq = i & 7, row = i >> 3;
            size_t src = ((size_t)tap * 256 + co0 + row) * 256 + ci0 + cq * 8;
            cp16(dH + sw128((unsigned)(row * 128 + cq * 16)), g_wa + src);
        }
        cp_commit();
    };

    for (int cc = 0; cc < 4; cc++) {
        const int ci0 = cc << 6;
        __syncthreads();   // previous chunk's reads of X and all A bufs complete
        // ---- stage X patch (rows h0-1..h0+2, cols -1..64) ----
        for (int i = tid; i < 4 * 66 * 8; i += 256) {
            int cq  = i & 7;
            int row = i >> 3;
            int hl  = row / 66;
            int wv  = row - hl * 66;
            int h = h0 + hl - 1;
            int w = wv - 1;
            bool ok = ((unsigned)h < 64u) && ((unsigned)w < 64u);
            size_t src = ok ? (((size_t)(h * 64 + w)) * 256 + ci0 + cq * 8) : 0;
            cp16z(sb + OFF_X + sw128((unsigned)((hl * 68 + wv) * 128 + cq * 16)),
                  xp + src, ok);
        }
        stageA(0, ci0, 0);     // commits {X, A0}
        stageA(1, ci0, 1);     // commits {A1}
        cp_wait0();
        __syncthreads();       // X, A0, A1 visible to all

        for (int tap = 0; tap < 9; tap++) {
            const int dh = tap / 3 - 1;
            const int dw = tap % 3 - 1;
            if (tap + 2 <= 8) stageA(tap + 2, ci0, (tap + 2) & 3);

            const unsigned AH = sb + OFF_A0 + (unsigned)(tap & 3) * A_BUF;

            unsigned b_rowoff[4];
            #pragma unroll
            for (int j = 0; j < 4; j++) {
                int hl = bn[j] >> 6, w = bn[j] & 63;
                b_rowoff[j] = (unsigned)(((hl + dh + 1) * 68 + (w + dw + 1)) * 128) + bk8;
            }

            #pragma unroll
            for (int ks = 0; ks < 4; ks++) {
                unsigned af[2][4], bf[4][4];
                #pragma unroll
                for (int mt = 0; mt < 2; mt++)
                    ldm_x4(af[mt], AH + sw128(a_rowoff[mt] + ks * 32u));
                #pragma unroll
                for (int j = 0; j < 4; j++)
                    ldm_x4(bf[j], sb + OFF_X + sw128(b_rowoff[j] + ks * 32u));
                #pragma unroll
                for (int mt = 0; mt < 2; mt++)
                    #pragma unroll
                    for (int nt = 0; nt < 8; nt++)
                        mma_f16(acc[mt][nt], af[mt],
                                bf[nt >> 1][nt & 1], bf[nt >> 1][(nt & 1) + 2]);
            }
            if (tap & 1) {      // publish staged buffers to all warps
                cp_wait0();
                __syncthreads();
            }
        }
    }

    const int r4 = lid >> 2, c2 = (lid & 3) << 1;
    #pragma unroll
    for (int mt = 0; mt < 2; mt++) {
        #pragma unroll
        for (int nt = 0; nt < 8; nt++) {
            int co  = co0 + wm * 32 + mt * 16 + r4;
            int pix = n0 + wn * 64 + nt * 8 + c2;
            size_t base = ((size_t)(b * 256 + co)) * NPIX + pix;
            *(unsigned*)(g_yt + base) = pk_h2(acc[mt][nt][0], acc[mt][nt][1]);
            *(unsigned*)(g_yt + base + (size_t)8 * NPIX) =
                pk_h2(acc[mt][nt][2], acc[mt][nt][3]);
        }
    }
}

// ---------------- kernel 5: ARMA solve, single-term fp16, 2 slices/CTA ----------------
#define PA_Y  0u
#define PA_GY 16384u
#define PA_GX 24576u
#define ARMA_SMEM 32768

__global__ __launch_bounds__(128, 4)
void arma_mma_kernel(float* __restrict__ out) {
    extern __shared__ char smem[];
    const unsigned sb = smem_u32(smem);
    const int tid = threadIdx.x;
    const int lid = tid & 31;
    const int wid = tid >> 5;
    const int c   = blockIdx.x & 255;
    const int bg  = blockIdx.x >> 8;
    const int slice0 = (2 * bg) * 256 + c;

    for (int i = tid; i < 1024; i += 128) {
        int r = i >> 3, cq = i & 7;
        int s = r >> 6, h = r & 63;
        size_t e = ((size_t)(slice0 + s * 256)) * 4096 + h * 64 + cq * 8;
        cp16(sb + PA_Y + sw128((unsigned)(r * 128 + cq * 16)), g_yt + e);
    }
    for (int i = tid; i < 512; i += 128) {
        int r = i >> 3, cq = i & 7;
        size_t e = (size_t)c * 4096 + r * 64 + cq * 8;
        unsigned swo = sw128((unsigned)(r * 128 + cq * 16));
        cp16(sb + PA_GY + swo, g_gyT + e);
        cp16(sb + PA_GX + swo, g_gx  + e);
    }
    cp_commit(); cp_wait0();
    __syncthreads();

    const int wm = wid & 1, wn = wid >> 1;
    unsigned a_rowoff[2];
    #pragma unroll
    for (int mt = 0; mt < 2; mt++) {
        int row = wm * 32 + mt * 16 + (lid & 7) + ((lid >> 3) & 1) * 8;
        a_rowoff[mt] = (unsigned)(row * 128) + ((unsigned)(lid >> 4)) * 16u;
    }
    unsigned b_off[4];
    #pragma unroll
    for (int j = 0; j < 4; j++)
        b_off[j] = (unsigned)((wn * 64 + j * 16 + (lid & 15)) * 128)
                 + ((unsigned)(lid >> 4)) * 16u;
    const int r4 = lid >> 2, cp2 = (lid & 3) << 1;

    // ---- stage 1: UT = GyT x Y ----
    float acc[2][8][4];
    #pragma unroll
    for (int mt = 0; mt < 2; mt++)
        #pragma unroll
        for (int nt = 0; nt < 8; nt++)
            #pragma unroll
            for (int k = 0; k < 4; k++) acc[mt][nt][k] = 0.f;

    #pragma unroll
    for (int ks = 0; ks < 4; ks++) {
        unsigned A[2][4], B[4][4];
        #pragma unroll
        for (int mt = 0; mt < 2; mt++)
            ldm_x4(A[mt], sb + PA_GY + sw128(a_rowoff[mt] + ks * 32u));
        #pragma unroll
        for (int j = 0; j < 4; j++)
            ldm_x4(B[j], sb + PA_Y + sw128(b_off[j] + ks * 32u));
        #pragma unroll
        for (int mt = 0; mt < 2; mt++)
            #pragma unroll
            for (int nt = 0; nt < 8; nt++)
                mma_f16(acc[mt][nt], A[mt],
                        B[nt >> 1][nt & 1], B[nt >> 1][(nt & 1) + 2]);
    }
    __syncthreads();

    // write UT (row = s*64 + j, col = h) into Y region
    #pragma unroll
    for (int mt = 0; mt < 2; mt++) {
        #pragma unroll
        for (int nt = 0; nt < 8; nt++) {
            int m = wm * 32 + mt * 16 + r4;
            int n = wn * 64 + nt * 8 + cp2;
            int row = (n & ~63) + m;
            int col = n & 63;
            *(unsigned*)(smem + PA_Y + sw128((unsigned)(row * 128 + col * 2))) =
                pk_h2(acc[mt][nt][0], acc[mt][nt][1]);
            *(unsigned*)(smem + PA_Y + sw128((unsigned)((row + 8) * 128 + col * 2))) =
                pk_h2(acc[mt][nt][2], acc[mt][nt][3]);
        }
    }
    __syncthreads();

    // ---- stage 2: out = Gx x UT ----
    float o[2][8][4];
    #pragma unroll
    for (int mt = 0; mt < 2; mt++)
        #pragma unroll
        for (int nt = 0; nt < 8; nt++)
            #pragma unroll
            for (int k = 0; k < 4; k++) o[mt][nt][k] = 0.f;

    #pragma unroll
    for (int ks = 0; ks < 4; ks++) {
        unsigned A[2][4], B[4][4];
        #pragma unroll
        for (int mt = 0; mt < 2; mt++)
            ldm_x4(A[mt], sb + PA_GX + sw128(a_rowoff[mt] + ks * 32u));
        #pragma unroll
        for (int j = 0; j < 4; j++)
            ldm_x4(B[j], sb + PA_Y + sw128(b_off[j] + ks * 32u));
        #pragma unroll
        for (int mt = 0; mt < 2; mt++)
            #pragma unroll
            for (int nt = 0; nt < 8; nt++)
                mma_f16(o[mt][nt], A[mt],
                        B[nt >> 1][nt & 1], B[nt >> 1][(nt & 1) + 2]);
    }

    #pragma unroll
    for (int mt = 0; mt < 2; mt++) {
        #pragma unroll
        for (int nt = 0; nt < 8; nt++) {
            int m = wm * 32 + mt * 16 + r4;
            int n = wn * 64 + nt * 8 + cp2;
            int s = n >> 6;
            int j = n & 63;
            float* O = out + ((size_t)(slice0 + s * 256)) * 4096;
            *(float2*)(O + m * 64 + j)       = make_float2(o[mt][nt][0], o[mt][nt][1]);
            *(float2*)(O + (m + 8) * 64 + j) = make_float2(o[mt][nt][2], o[mt][nt][3]);
        }
    }
}

// ---------------- launcher ----------------
extern "C" void kernel_launch(void* const* d_in, const int* in_sizes, int n_in,
                              void* d_out, int out_size) {
    const float* x     = (const float*)d_in[0];
    const float* w     = (const float*)d_in[1];
    const float* alpha = (const float*)d_in[2];
    float* out = (float*)d_out;

    cudaFuncSetAttribute(conv_mma_kernel,
                         cudaFuncAttributeMaxDynamicSharedMemorySize, CONV_SMEM);
    cudaFuncSetAttribute(arma_mma_kernel,
                         cudaFuncAttributeMaxDynamicSharedMemorySize, ARMA_SMEM);

    wa_kernel<<<CCH, 256>>>(w);
    gmat_kernel<<<CCH, 128>>>(alpha);
    xt_kernel<<<dim3(64, 4, 32), 256>>>(x);
    conv_mma_kernel<<<dim3(32, 2, 32), 256, CONV_SMEM>>>();
    arma_mma_kernel<<<16 * 256, 128, ARMA_SMEM>>>(out);
}